// round 10
// baseline (speedup 1.0000x reference)
#include <cuda_runtime.h>
#include <cstdint>

#define M_TOK 16384   // B*S tokens
#define K_DIM 2048    // DIN
#define N_DIM 2048    // DOUT

// ---------------------------------------------------------------------------
// Scratch (__device__ globals; no allocations allowed)
// ---------------------------------------------------------------------------
__device__ int8_t g_xq[(size_t)M_TOK * K_DIM];      // 32 MB quantized activations
__device__ float  g_xscale[M_TOK];                  // per-token scale
__device__ int8_t g_w[(size_t)N_DIM * K_DIM];       // 4 MB ternary weights as int8
__device__ int    g_acc[(size_t)M_TOK * N_DIM];     // 128 MB int32 GEMM output

// ---------------------------------------------------------------------------
// Block reductions (256 threads, 8 warps)
// ---------------------------------------------------------------------------
__device__ __forceinline__ void block_reduce_sum4(float& a, float& b, float& c, float& d,
                                                  float* sh) {
    #pragma unroll
    for (int o = 16; o > 0; o >>= 1) {
        a += __shfl_xor_sync(0xFFFFFFFFu, a, o);
        b += __shfl_xor_sync(0xFFFFFFFFu, b, o);
        c += __shfl_xor_sync(0xFFFFFFFFu, c, o);
        d += __shfl_xor_sync(0xFFFFFFFFu, d, o);
    }
    int w = threadIdx.x >> 5, l = threadIdx.x & 31;
    if (l == 0) { sh[w] = a; sh[w+8] = b; sh[w+16] = c; sh[w+24] = d; }
    __syncthreads();
    if (threadIdx.x < 32) {
        float va = (l < 8) ? sh[l]      : 0.f;
        float vb = (l < 8) ? sh[l + 8]  : 0.f;
        float vc = (l < 8) ? sh[l + 16] : 0.f;
        float vd = (l < 8) ? sh[l + 24] : 0.f;
        #pragma unroll
        for (int o = 4; o > 0; o >>= 1) {
            va += __shfl_xor_sync(0xFFFFFFFFu, va, o);
            vb += __shfl_xor_sync(0xFFFFFFFFu, vb, o);
            vc += __shfl_xor_sync(0xFFFFFFFFu, vc, o);
            vd += __shfl_xor_sync(0xFFFFFFFFu, vd, o);
        }
        if (l == 0) { sh[32] = va; sh[33] = vb; sh[34] = vc; sh[35] = vd; }
    }
    __syncthreads();
    a = sh[32]; b = sh[33]; c = sh[34]; d = sh[35];
    __syncthreads();
}

__device__ __forceinline__ void block_reduce_max4(float& a, float& b, float& c, float& d,
                                                  float* sh) {
    #pragma unroll
    for (int o = 16; o > 0; o >>= 1) {
        a = fmaxf(a, __shfl_xor_sync(0xFFFFFFFFu, a, o));
        b = fmaxf(b, __shfl_xor_sync(0xFFFFFFFFu, b, o));
        c = fmaxf(c, __shfl_xor_sync(0xFFFFFFFFu, c, o));
        d = fmaxf(d, __shfl_xor_sync(0xFFFFFFFFu, d, o));
    }
    int w = threadIdx.x >> 5, l = threadIdx.x & 31;
    if (l == 0) { sh[w] = a; sh[w+8] = b; sh[w+16] = c; sh[w+24] = d; }
    __syncthreads();
    if (threadIdx.x < 32) {
        float va = (l < 8) ? sh[l]      : -1e30f;
        float vb = (l < 8) ? sh[l + 8]  : -1e30f;
        float vc = (l < 8) ? sh[l + 16] : -1e30f;
        float vd = (l < 8) ? sh[l + 24] : -1e30f;
        #pragma unroll
        for (int o = 4; o > 0; o >>= 1) {
            va = fmaxf(va, __shfl_xor_sync(0xFFFFFFFFu, va, o));
            vb = fmaxf(vb, __shfl_xor_sync(0xFFFFFFFFu, vb, o));
            vc = fmaxf(vc, __shfl_xor_sync(0xFFFFFFFFu, vc, o));
            vd = fmaxf(vd, __shfl_xor_sync(0xFFFFFFFFu, vd, o));
        }
        if (l == 0) { sh[32] = va; sh[33] = vb; sh[34] = vc; sh[35] = vd; }
    }
    __syncthreads();
    a = sh[32]; b = sh[33]; c = sh[34]; d = sh[35];
    __syncthreads();
}

// ---------------------------------------------------------------------------
// Kernel 1: fused input LayerNorm + per-token int8 absmax quantization.
// 4 token rows per block; all 8 LDG.128 issued before compute (latency hiding).
// Per-row element->thread mapping and reduction order unchanged (bit-exact).
// Clamps removed: |v * (127/amax)| <= 127 by construction (never binds, also
// never binds in the reference).
// Blocks [M_TOK/4 ..) repack the ternary weights.
// ---------------------------------------------------------------------------
#define LNQ_BLOCKS (M_TOK / 4)                        // 4096
#define PACK_BLOCKS 2048                              // 2048*512 int4 = 4M elems
__global__ __launch_bounds__(256) void ln_quant_kernel(const float* __restrict__ x,
                                                       const int* __restrict__ wt) {
    const int t = threadIdx.x;

    if (blockIdx.x >= LNQ_BLOCKS) {
        // weight repack role: int32 ternary -> int8
        int base = (int)(blockIdx.x - LNQ_BLOCKS) * 512 + t * 2;
        #pragma unroll
        for (int l = 0; l < 2; l++) {
            int idx = base + l;
            int4 v = __ldcs(&((const int4*)wt)[idx]);
            char4 c;
            c.x = (char)v.x; c.y = (char)v.y; c.z = (char)v.z; c.w = (char)v.w;
            ((char4*)g_w)[idx] = c;
        }
        return;
    }

    __shared__ float sh[36];
    const int row0 = (int)blockIdx.x * 4;
    const float4* xr0 = (const float4*)(x + (size_t)(row0 + 0) * K_DIM);
    const float4* xr1 = (const float4*)(x + (size_t)(row0 + 1) * K_DIM);
    const float4* xr2 = (const float4*)(x + (size_t)(row0 + 2) * K_DIM);
    const float4* xr3 = (const float4*)(x + (size_t)(row0 + 3) * K_DIM);

    // issue all 8 vector loads up front (MLP=8)
    float4 a0 = __ldcs(&xr0[t]);
    float4 b0 = __ldcs(&xr0[t + 256]);
    float4 a1 = __ldcs(&xr1[t]);
    float4 b1 = __ldcs(&xr1[t + 256]);
    float4 a2 = __ldcs(&xr2[t]);
    float4 b2 = __ldcs(&xr2[t + 256]);
    float4 a3 = __ldcs(&xr3[t]);
    float4 b3 = __ldcs(&xr3[t + 256]);

    float v0[8], v1[8], v2[8], v3[8];
    v0[0]=a0.x; v0[1]=a0.y; v0[2]=a0.z; v0[3]=a0.w;
    v0[4]=b0.x; v0[5]=b0.y; v0[6]=b0.z; v0[7]=b0.w;
    v1[0]=a1.x; v1[1]=a1.y; v1[2]=a1.z; v1[3]=a1.w;
    v1[4]=b1.x; v1[5]=b1.y; v1[6]=b1.z; v1[7]=b1.w;
    v2[0]=a2.x; v2[1]=a2.y; v2[2]=a2.z; v2[3]=a2.w;
    v2[4]=b2.x; v2[5]=b2.y; v2[6]=b2.z; v2[7]=b2.w;
    v3[0]=a3.x; v3[1]=a3.y; v3[2]=a3.z; v3[3]=a3.w;
    v3[4]=b3.x; v3[5]=b3.y; v3[6]=b3.z; v3[7]=b3.w;

    float s0=0.f, ss0=0.f, s1=0.f, ss1=0.f, s2=0.f, ss2=0.f, s3=0.f, ss3=0.f;
    #pragma unroll
    for (int i = 0; i < 8; i++) {
        s0 += v0[i]; ss0 += v0[i]*v0[i];
        s1 += v1[i]; ss1 += v1[i]*v1[i];
        s2 += v2[i]; ss2 += v2[i]*v2[i];
        s3 += v3[i]; ss3 += v3[i]*v3[i];
    }
    block_reduce_sum4(s0, ss0, s1, ss1, sh);
    block_reduce_sum4(s2, ss2, s3, ss3, sh);

    const float invn = 1.0f / (float)K_DIM;
    float mu0 = s0 * invn, rstd0 = rsqrtf(fmaxf(ss0 * invn - mu0 * mu0, 0.f) + 1e-5f);
    float mu1 = s1 * invn, rstd1 = rsqrtf(fmaxf(ss1 * invn - mu1 * mu1, 0.f) + 1e-5f);
    float mu2 = s2 * invn, rstd2 = rsqrtf(fmaxf(ss2 * invn - mu2 * mu2, 0.f) + 1e-5f);
    float mu3 = s3 * invn, rstd3 = rsqrtf(fmaxf(ss3 * invn - mu3 * mu3, 0.f) + 1e-5f);

    float m0 = 0.f, m1 = 0.f, m2 = 0.f, m3 = 0.f;
    #pragma unroll
    for (int i = 0; i < 8; i++) {
        v0[i] = (v0[i] - mu0) * rstd0; m0 = fmaxf(m0, fabsf(v0[i]));
        v1[i] = (v1[i] - mu1) * rstd1; m1 = fmaxf(m1, fabsf(v1[i]));
        v2[i] = (v2[i] - mu2) * rstd2; m2 = fmaxf(m2, fabsf(v2[i]));
        v3[i] = (v3[i] - mu3) * rstd3; m3 = fmaxf(m3, fabsf(v3[i]));
    }
    block_reduce_max4(m0, m1, m2, m3, sh);
    m0 = fmaxf(m0, 1e-5f);
    m1 = fmaxf(m1, 1e-5f);
    m2 = fmaxf(m2, 1e-5f);
    m3 = fmaxf(m3, 1e-5f);
    float i0 = 127.0f / m0, i1 = 127.0f / m1, i2 = 127.0f / m2, i3 = 127.0f / m3;

    // quantize (round-half-even via rintf; clamp provably redundant)
    char4* d0 = (char4*)(g_xq + (size_t)(row0 + 0) * K_DIM);
    char4* d1 = (char4*)(g_xq + (size_t)(row0 + 1) * K_DIM);
    char4* d2 = (char4*)(g_xq + (size_t)(row0 + 2) * K_DIM);
    char4* d3 = (char4*)(g_xq + (size_t)(row0 + 3) * K_DIM);
    char4 c;
    c.x = (char)(int)rintf(v0[0]*i0); c.y = (char)(int)rintf(v0[1]*i0);
    c.z = (char)(int)rintf(v0[2]*i0); c.w = (char)(int)rintf(v0[3]*i0);
    d0[t] = c;
    c.x = (char)(int)rintf(v0[4]*i0); c.y = (char)(int)rintf(v0[5]*i0);
    c.z = (char)(int)rintf(v0[6]*i0); c.w = (char)(int)rintf(v0[7]*i0);
    d0[t + 256] = c;
    c.x = (char)(int)rintf(v1[0]*i1); c.y = (char)(int)rintf(v1[1]*i1);
    c.z = (char)(int)rintf(v1[2]*i1); c.w = (char)(int)rintf(v1[3]*i1);
    d1[t] = c;
    c.x = (char)(int)rintf(v1[4]*i1); c.y = (char)(int)rintf(v1[5]*i1);
    c.z = (char)(int)rintf(v1[6]*i1); c.w = (char)(int)rintf(v1[7]*i1);
    d1[t + 256] = c;
    c.x = (char)(int)rintf(v2[0]*i2); c.y = (char)(int)rintf(v2[1]*i2);
    c.z = (char)(int)rintf(v2[2]*i2); c.w = (char)(int)rintf(v2[3]*i2);
    d2[t] = c;
    c.x = (char)(int)rintf(v2[4]*i2); c.y = (char)(int)rintf(v2[5]*i2);
    c.z = (char)(int)rintf(v2[6]*i2); c.w = (char)(int)rintf(v2[7]*i2);
    d2[t + 256] = c;
    c.x = (char)(int)rintf(v3[0]*i3); c.y = (char)(int)rintf(v3[1]*i3);
    c.z = (char)(int)rintf(v3[2]*i3); c.w = (char)(int)rintf(v3[3]*i3);
    d3[t] = c;
    c.x = (char)(int)rintf(v3[4]*i3); c.y = (char)(int)rintf(v3[5]*i3);
    c.z = (char)(int)rintf(v3[6]*i3); c.w = (char)(int)rintf(v3[7]*i3);
    d3[t + 256] = c;

    if (t == 0) {
        g_xscale[row0 + 0] = m0 * (1.0f / 127.0f);
        g_xscale[row0 + 1] = m1 * (1.0f / 127.0f);
        g_xscale[row0 + 2] = m2 * (1.0f / 127.0f);
        g_xscale[row0 + 3] = m3 * (1.0f / 127.0f);
    }
}

// ---------------------------------------------------------------------------
// Kernel 2: int8 tensor-core GEMM via mma.sync.m16n8k32.
// CTA tile 128x256, K staged 128B, 8 warps (2x4), warp tile 64x64,
// 4-stage cp.async pipeline.  acc[m][n] = sum_k xq[m][k] * w[n][k]
// Measured at ~95% of the sm_100 legacy-IMMA pipe rate (~1024 MAC/cyc/SM).
// ---------------------------------------------------------------------------
#define BM  128
#define BN  256
#define BKB 128   // K-bytes per stage
#define NIT (K_DIM / BKB)   // 16
#define NSTAGE 4
#define A_BYTES (BM * BKB)                // 16 KB
#define B_BYTES (BN * BKB)                // 32 KB
#define STAGE_BYTES (A_BYTES + B_BYTES)   // 48 KB
#define SMEM_DYN (NSTAGE * STAGE_BYTES)   // 192 KB

__device__ __forceinline__ uint32_t smem_u32(const void* p) {
    uint32_t a;
    asm("{ .reg .u64 t; cvta.to.shared.u64 t, %1; cvt.u32.u64 %0, t; }" : "=r"(a) : "l"(p));
    return a;
}

// swizzled byte offset within a [rows x 128B] tile
__device__ __forceinline__ uint32_t swz(int row, int c) {
    return (uint32_t)(row * 128 + ((c ^ (row & 7)) << 4));
}

__device__ __forceinline__ void cp16(uint32_t saddr, const void* g) {
    asm volatile("cp.async.cg.shared.global [%0], [%1], 16;" :: "r"(saddr), "l"(g));
}

__device__ __forceinline__ void ldsm4(uint32_t* r, uint32_t addr) {
    asm volatile("ldmatrix.sync.aligned.m8n8.x4.shared.b16 {%0,%1,%2,%3}, [%4];"
                 : "=r"(r[0]), "=r"(r[1]), "=r"(r[2]), "=r"(r[3]) : "r"(addr));
}

__device__ __forceinline__ void mma_s8(int* c, const uint32_t* a, const uint32_t* b) {
    asm volatile(
        "mma.sync.aligned.m16n8k32.row.col.s32.s8.s8.s32 "
        "{%0,%1,%2,%3}, {%4,%5,%6,%7}, {%8,%9}, {%0,%1,%2,%3};"
        : "+r"(c[0]), "+r"(c[1]), "+r"(c[2]), "+r"(c[3])
        : "r"(a[0]), "r"(a[1]), "r"(a[2]), "r"(a[3]), "r"(b[0]), "r"(b[1]));
}

__global__ __launch_bounds__(256, 1) void gemm_kernel() {
    extern __shared__ uint8_t smem[];

    const int tid  = threadIdx.x;
    const int wid  = tid >> 5;
    const int lane = tid & 31;
    const int wm   = wid >> 2;          // 0..1 -> m offset wm*64
    const int wn   = wid & 3;           // 0..3 -> n offset wn*64
    const int bm   = (int)blockIdx.y * BM;
    const int bn   = (int)blockIdx.x * BN;
    const uint32_t sbase = smem_u32(smem);

    int acc[4][8][4];
    #pragma unroll
    for (int i = 0; i < 4; i++)
        #pragma unroll
        for (int j = 0; j < 8; j++)
            #pragma unroll
            for (int r = 0; r < 4; r++) acc[i][j][r] = 0;

    // cooperative load of one stage: A 1024 + B 2048 chunks of 16B = 12/thread
    auto load_stage = [&](int st, int k0) {
        uint32_t sa = sbase + st * STAGE_BYTES;
        uint32_t sb = sa + A_BYTES;
        #pragma unroll
        for (int i = 0; i < 12; i++) {
            int idx = tid + i * 256;        // 0..3071
            if (idx < 1024) {
                int row = idx >> 3, c = idx & 7;
                cp16(sa + swz(row, c), g_xq + (size_t)(bm + row) * K_DIM + k0 + c * 16);
            } else {
                int j = idx - 1024;
                int row = j >> 3, c = j & 7;
                cp16(sb + swz(row, c), g_w + (size_t)(bn + row) * K_DIM + k0 + c * 16);
            }
        }
    };

    // prologue: 3 stages in flight
    load_stage(0, 0);
    asm volatile("cp.async.commit_group;" ::: "memory");
    load_stage(1, BKB);
    asm volatile("cp.async.commit_group;" ::: "memory");
    load_stage(2, 2 * BKB);
    asm volatile("cp.async.commit_group;" ::: "memory");

    const int lrow = lane & 15;         // ldmatrix row within 16
    const int lchk = lane >> 4;         // ldmatrix chunk select

    for (int it = 0; it < NIT; ++it) {
        asm volatile("cp.async.wait_group 2;" ::: "memory");
        __syncthreads();

        // issue next load (overwrites stage consumed last iter; sync above guards)
        int nt = it + 3;
        if (nt < NIT) load_stage(nt % NSTAGE, nt * BKB);
        asm volatile("cp.async.commit_group;" ::: "memory");

        const int st = it % NSTAGE;
        const uint32_t sa = sbase + st * STAGE_BYTES;
        const uint32_t sb = sa + A_BYTES;

        #pragma unroll
        for (int ks = 0; ks < 4; ks++) {    // four k32 steps per 128B stage
            uint32_t a[4][4];
            #pragma unroll
            for (int i = 0; i < 4; i++) {
                int row = wm * 64 + i * 16 + lrow;
                ldsm4(a[i], sa + swz(row, ks * 2 + lchk));
            }
            uint32_t b[8][2];
            #pragma unroll
            for (int jj = 0; jj < 4; jj++) {
                uint32_t r[4];
                int row = wn * 64 + jj * 16 + lrow;
                ldsm4(r, sb + swz(row, ks * 2 + lchk));
                b[jj*2][0]   = r[0]; b[jj*2][1]   = r[2];
                b[jj*2+1][0] = r[1]; b[jj*2+1][1] = r[3];
            }
            #pragma unroll
            for (int i = 0; i < 4; i++)
                #pragma unroll
                for (int j = 0; j < 8; j++)
                    mma_s8(acc[i][j], a[i], b[j]);
        }
    }

    // epilogue: direct int2 streaming stores (acc has no reuse until ln_out)
    #pragma unroll
    for (int i = 0; i < 4; i++) {
        #pragma unroll
        for (int j = 0; j < 8; j++) {
            int r0  = bm + wm * 64 + i * 16 + (lane >> 2);
            int col = bn + wn * 64 + j * 8 + (lane & 3) * 2;
            int2 v0; v0.x = acc[i][j][0]; v0.y = acc[i][j][1];
            int2 v1; v1.x = acc[i][j][2]; v1.y = acc[i][j][3];
            __stcs((int2*)(g_acc + (size_t)r0 * N_DIM + col), v0);
            __stcs((int2*)(g_acc + (size_t)(r0 + 8) * N_DIM + col), v1);
        }
    }
}

// ---------------------------------------------------------------------------
// Kernel 3: fused dequant (x_scale[t] * w_scale[o]) + output LayerNorm.
// 2 token rows per block; per-row FP reduction order unchanged.
// ---------------------------------------------------------------------------
__global__ __launch_bounds__(256) void ln_out_kernel(const float* __restrict__ wscale,
                                                     float* __restrict__ out) {
    __shared__ float sh[36];
    const int row0 = (int)blockIdx.x * 2;
    const int row1 = row0 + 1;
    const int t = threadIdx.x;
    const float st0 = g_xscale[row0];
    const float st1 = g_xscale[row1];

    const int4* ar0 = (const int4*)(g_acc + (size_t)row0 * N_DIM);
    const int4* ar1 = (const int4*)(g_acc + (size_t)row1 * N_DIM);
    const float4* ws = (const float4*)wscale;

    int4 a0 = __ldcs(&ar0[t]);
    int4 b0 = __ldcs(&ar0[t + 256]);
    int4 a1 = __ldcs(&ar1[t]);
    int4 b1 = __ldcs(&ar1[t + 256]);
    float4 w0 = __ldg(&ws[t]);
    float4 w1 = __ldg(&ws[t + 256]);

    float v0[8], v1[8];
    v0[0] = (float)a0.x * st0 * w0.x;
    v0[1] = (float)a0.y * st0 * w0.y;
    v0[2] = (float)a0.z * st0 * w0.z;
    v0[3] = (float)a0.w * st0 * w0.w;
    v0[4] = (float)b0.x * st0 * w1.x;
    v0[5] = (float)b0.y * st0 * w1.y;
    v0[6] = (float)b0.z * st0 * w1.z;
    v0[7] = (float)b0.w * st0 * w1.w;
    v1[0] = (float)a1.x * st1 * w0.x;
    v1[1] = (float)a1.y * st1 * w0.y;
    v1[2] = (float)a1.z * st1 * w0.z;
    v1[3] = (float)a1.w * st1 * w0.w;
    v1[4] = (float)b1.x * st1 * w1.x;
    v1[5] = (float)b1.y * st1 * w1.y;
    v1[6] = (float)b1.z * st1 * w1.z;
    v1[7] = (float)b1.w * st1 * w1.w;

    float s0 = 0.f, ss0 = 0.f, s1 = 0.f, ss1 = 0.f;
    #pragma unroll
    for (int i = 0; i < 8; i++) {
        s0 += v0[i]; ss0 += v0[i]*v0[i];
        s1 += v1[i]; ss1 += v1[i]*v1[i];
    }
    block_reduce_sum4(s0, ss0, s1, ss1, sh);

    const float invn = 1.0f / (float)N_DIM;
    float mu0  = s0 * invn;
    float var0 = fmaxf(ss0 * invn - mu0 * mu0, 0.f);
    float rstd0 = rsqrtf(var0 + 1e-5f);
    float mu1  = s1 * invn;
    float var1 = fmaxf(ss1 * invn - mu1 * mu1, 0.f);
    float rstd1 = rsqrtf(var1 + 1e-5f);

    float4* d0 = (float4*)(out + (size_t)row0 * N_DIM);
    float4* d1 = (float4*)(out + (size_t)row1 * N_DIM);
    float4 o;
    o.x = (v0[0]-mu0)*rstd0; o.y = (v0[1]-mu0)*rstd0;
    o.z = (v0[2]-mu0)*rstd0; o.w = (v0[3]-mu0)*rstd0;
    __stcs(&d0[t], o);
    o.x = (v0[4]-mu0)*rstd0; o.y = (v0[5]-mu0)*rstd0;
    o.z = (v0[6]-mu0)*rstd0; o.w = (v0[7]-mu0)*rstd0;
    __stcs(&d0[t + 256], o);
    o.x = (v1[0]-mu1)*rstd1; o.y = (v1[1]-mu1)*rstd1;
    o.z = (v1[2]-mu1)*rstd1; o.w = (v1[3]-mu1)*rstd1;
    __stcs(&d1[t], o);
    o.x = (v1[4]-mu1)*rstd1; o.y = (v1[5]-mu1)*rstd1;
    o.z = (v1[6]-mu1)*rstd1; o.w = (v1[7]-mu1)*rstd1;
    __stcs(&d1[t + 256], o);
}

// ---------------------------------------------------------------------------
// Launch (3 kernels: ln_quant+pack fused, gemm, ln_out)
// ---------------------------------------------------------------------------
extern "C" void kernel_launch(void* const* d_in, const int* in_sizes, int n_in,
                              void* d_out, int out_size) {
    const float* x  = (const float*)d_in[0];          // [4,4096,2048] f32
    const int*   wt = (const int*)d_in[1];            // [2048,2048] i32 ternary
    const float* ws = (const float*)d_in[2];          // [2048] f32
    float* out = (float*)d_out;                       // [4,4096,2048] f32

    cudaFuncSetAttribute(gemm_kernel, cudaFuncAttributeMaxDynamicSharedMemorySize, SMEM_DYN);

    ln_quant_kernel<<<LNQ_BLOCKS + PACK_BLOCKS, 256>>>(x, wt);
    dim3 grid(N_DIM / BN, M_TOK / BM);                // (8, 128) = 1024 CTAs
    gemm_kernel<<<grid, 256, SMEM_DYN>>>();
    ln_out_kernel<<<M_TOK / 2, 256>>>(ws, out);
}

// round 12
// speedup vs baseline: 1.0028x; 1.0028x over previous
#include <cuda_runtime.h>
#include <cuda_fp16.h>
#include <cstdint>

#define M_TOK 16384   // B*S tokens
#define K_DIM 2048    // DIN
#define N_DIM 2048    // DOUT

// ---------------------------------------------------------------------------
// Scratch (__device__ globals; no allocations allowed)
// ---------------------------------------------------------------------------
__device__ int8_t g_xq[(size_t)M_TOK * K_DIM];      // 32 MB quantized activations
__device__ float  g_xscale[M_TOK];                  // per-token scale
__device__ int8_t g_w[(size_t)N_DIM * K_DIM];       // 4 MB ternary weights as int8
__device__ __half g_vh[(size_t)M_TOK * N_DIM];      // 64 MB dequantized GEMM output (f16)

// ---------------------------------------------------------------------------
// Block reductions (256 threads, 8 warps)
// ---------------------------------------------------------------------------
__device__ __forceinline__ void block_reduce_sum4(float& a, float& b, float& c, float& d,
                                                  float* sh) {
    #pragma unroll
    for (int o = 16; o > 0; o >>= 1) {
        a += __shfl_xor_sync(0xFFFFFFFFu, a, o);
        b += __shfl_xor_sync(0xFFFFFFFFu, b, o);
        c += __shfl_xor_sync(0xFFFFFFFFu, c, o);
        d += __shfl_xor_sync(0xFFFFFFFFu, d, o);
    }
    int w = threadIdx.x >> 5, l = threadIdx.x & 31;
    if (l == 0) { sh[w] = a; sh[w+8] = b; sh[w+16] = c; sh[w+24] = d; }
    __syncthreads();
    if (threadIdx.x < 32) {
        float va = (l < 8) ? sh[l]      : 0.f;
        float vb = (l < 8) ? sh[l + 8]  : 0.f;
        float vc = (l < 8) ? sh[l + 16] : 0.f;
        float vd = (l < 8) ? sh[l + 24] : 0.f;
        #pragma unroll
        for (int o = 4; o > 0; o >>= 1) {
            va += __shfl_xor_sync(0xFFFFFFFFu, va, o);
            vb += __shfl_xor_sync(0xFFFFFFFFu, vb, o);
            vc += __shfl_xor_sync(0xFFFFFFFFu, vc, o);
            vd += __shfl_xor_sync(0xFFFFFFFFu, vd, o);
        }
        if (l == 0) { sh[32] = va; sh[33] = vb; sh[34] = vc; sh[35] = vd; }
    }
    __syncthreads();
    a = sh[32]; b = sh[33]; c = sh[34]; d = sh[35];
    __syncthreads();
}

__device__ __forceinline__ void block_reduce_max4(float& a, float& b, float& c, float& d,
                                                  float* sh) {
    #pragma unroll
    for (int o = 16; o > 0; o >>= 1) {
        a = fmaxf(a, __shfl_xor_sync(0xFFFFFFFFu, a, o));
        b = fmaxf(b, __shfl_xor_sync(0xFFFFFFFFu, b, o));
        c = fmaxf(c, __shfl_xor_sync(0xFFFFFFFFu, c, o));
        d = fmaxf(d, __shfl_xor_sync(0xFFFFFFFFu, d, o));
    }
    int w = threadIdx.x >> 5, l = threadIdx.x & 31;
    if (l == 0) { sh[w] = a; sh[w+8] = b; sh[w+16] = c; sh[w+24] = d; }
    __syncthreads();
    if (threadIdx.x < 32) {
        float va = (l < 8) ? sh[l]      : -1e30f;
        float vb = (l < 8) ? sh[l + 8]  : -1e30f;
        float vc = (l < 8) ? sh[l + 16] : -1e30f;
        float vd = (l < 8) ? sh[l + 24] : -1e30f;
        #pragma unroll
        for (int o = 4; o > 0; o >>= 1) {
            va = fmaxf(va, __shfl_xor_sync(0xFFFFFFFFu, va, o));
            vb = fmaxf(vb, __shfl_xor_sync(0xFFFFFFFFu, vb, o));
            vc = fmaxf(vc, __shfl_xor_sync(0xFFFFFFFFu, vc, o));
            vd = fmaxf(vd, __shfl_xor_sync(0xFFFFFFFFu, vd, o));
        }
        if (l == 0) { sh[32] = va; sh[33] = vb; sh[34] = vc; sh[35] = vd; }
    }
    __syncthreads();
    a = sh[32]; b = sh[33]; c = sh[34]; d = sh[35];
    __syncthreads();
}

// ---------------------------------------------------------------------------
// Kernel 1: fused input LayerNorm + per-token int8 absmax quantization.
// 4 token rows per block; all 8 LDG.128 issued before compute.
// Blocks [M_TOK/4 ..) repack the ternary weights.
// ---------------------------------------------------------------------------
#define LNQ_BLOCKS (M_TOK / 4)                        // 4096
#define PACK_BLOCKS 2048
__global__ __launch_bounds__(256) void ln_quant_kernel(const float* __restrict__ x,
                                                       const int* __restrict__ wt) {
    const int t = threadIdx.x;

    if (blockIdx.x >= LNQ_BLOCKS) {
        int base = (int)(blockIdx.x - LNQ_BLOCKS) * 512 + t * 2;
        #pragma unroll
        for (int l = 0; l < 2; l++) {
            int idx = base + l;
            int4 v = __ldcs(&((const int4*)wt)[idx]);
            char4 c;
            c.x = (char)v.x; c.y = (char)v.y; c.z = (char)v.z; c.w = (char)v.w;
            ((char4*)g_w)[idx] = c;
        }
        return;
    }

    __shared__ float sh[36];
    const int row0 = (int)blockIdx.x * 4;
    const float4* xr0 = (const float4*)(x + (size_t)(row0 + 0) * K_DIM);
    const float4* xr1 = (const float4*)(x + (size_t)(row0 + 1) * K_DIM);
    const float4* xr2 = (const float4*)(x + (size_t)(row0 + 2) * K_DIM);
    const float4* xr3 = (const float4*)(x + (size_t)(row0 + 3) * K_DIM);

    float4 a0 = __ldcs(&xr0[t]);
    float4 b0 = __ldcs(&xr0[t + 256]);
    float4 a1 = __ldcs(&xr1[t]);
    float4 b1 = __ldcs(&xr1[t + 256]);
    float4 a2 = __ldcs(&xr2[t]);
    float4 b2 = __ldcs(&xr2[t + 256]);
    float4 a3 = __ldcs(&xr3[t]);
    float4 b3 = __ldcs(&xr3[t + 256]);

    float v0[8], v1[8], v2[8], v3[8];
    v0[0]=a0.x; v0[1]=a0.y; v0[2]=a0.z; v0[3]=a0.w;
    v0[4]=b0.x; v0[5]=b0.y; v0[6]=b0.z; v0[7]=b0.w;
    v1[0]=a1.x; v1[1]=a1.y; v1[2]=a1.z; v1[3]=a1.w;
    v1[4]=b1.x; v1[5]=b1.y; v1[6]=b1.z; v1[7]=b1.w;
    v2[0]=a2.x; v2[1]=a2.y; v2[2]=a2.z; v2[3]=a2.w;
    v2[4]=b2.x; v2[5]=b2.y; v2[6]=b2.z; v2[7]=b2.w;
    v3[0]=a3.x; v3[1]=a3.y; v3[2]=a3.z; v3[3]=a3.w;
    v3[4]=b3.x; v3[5]=b3.y; v3[6]=b3.z; v3[7]=b3.w;

    float s0=0.f, ss0=0.f, s1=0.f, ss1=0.f, s2=0.f, ss2=0.f, s3=0.f, ss3=0.f;
    #pragma unroll
    for (int i = 0; i < 8; i++) {
        s0 += v0[i]; ss0 += v0[i]*v0[i];
        s1 += v1[i]; ss1 += v1[i]*v1[i];
        s2 += v2[i]; ss2 += v2[i]*v2[i];
        s3 += v3[i]; ss3 += v3[i]*v3[i];
    }
    block_reduce_sum4(s0, ss0, s1, ss1, sh);
    block_reduce_sum4(s2, ss2, s3, ss3, sh);

    const float invn = 1.0f / (float)K_DIM;
    float mu0 = s0 * invn, rstd0 = rsqrtf(fmaxf(ss0 * invn - mu0 * mu0, 0.f) + 1e-5f);
    float mu1 = s1 * invn, rstd1 = rsqrtf(fmaxf(ss1 * invn - mu1 * mu1, 0.f) + 1e-5f);
    float mu2 = s2 * invn, rstd2 = rsqrtf(fmaxf(ss2 * invn - mu2 * mu2, 0.f) + 1e-5f);
    float mu3 = s3 * invn, rstd3 = rsqrtf(fmaxf(ss3 * invn - mu3 * mu3, 0.f) + 1e-5f);

    float m0 = 0.f, m1 = 0.f, m2 = 0.f, m3 = 0.f;
    #pragma unroll
    for (int i = 0; i < 8; i++) {
        v0[i] = (v0[i] - mu0) * rstd0; m0 = fmaxf(m0, fabsf(v0[i]));
        v1[i] = (v1[i] - mu1) * rstd1; m1 = fmaxf(m1, fabsf(v1[i]));
        v2[i] = (v2[i] - mu2) * rstd2; m2 = fmaxf(m2, fabsf(v2[i]));
        v3[i] = (v3[i] - mu3) * rstd3; m3 = fmaxf(m3, fabsf(v3[i]));
    }
    block_reduce_max4(m0, m1, m2, m3, sh);
    m0 = fmaxf(m0, 1e-5f);
    m1 = fmaxf(m1, 1e-5f);
    m2 = fmaxf(m2, 1e-5f);
    m3 = fmaxf(m3, 1e-5f);
    float i0 = 127.0f / m0, i1 = 127.0f / m1, i2 = 127.0f / m2, i3 = 127.0f / m3;

    char4* d0 = (char4*)(g_xq + (size_t)(row0 + 0) * K_DIM);
    char4* d1 = (char4*)(g_xq + (size_t)(row0 + 1) * K_DIM);
    char4* d2 = (char4*)(g_xq + (size_t)(row0 + 2) * K_DIM);
    char4* d3 = (char4*)(g_xq + (size_t)(row0 + 3) * K_DIM);
    char4 c;
    c.x = (char)(int)rintf(v0[0]*i0); c.y = (char)(int)rintf(v0[1]*i0);
    c.z = (char)(int)rintf(v0[2]*i0); c.w = (char)(int)rintf(v0[3]*i0);
    d0[t] = c;
    c.x = (char)(int)rintf(v0[4]*i0); c.y = (char)(int)rintf(v0[5]*i0);
    c.z = (char)(int)rintf(v0[6]*i0); c.w = (char)(int)rintf(v0[7]*i0);
    d0[t + 256] = c;
    c.x = (char)(int)rintf(v1[0]*i1); c.y = (char)(int)rintf(v1[1]*i1);
    c.z = (char)(int)rintf(v1[2]*i1); c.w = (char)(int)rintf(v1[3]*i1);
    d1[t] = c;
    c.x = (char)(int)rintf(v1[4]*i1); c.y = (char)(int)rintf(v1[5]*i1);
    c.z = (char)(int)rintf(v1[6]*i1); c.w = (char)(int)rintf(v1[7]*i1);
    d1[t + 256] = c;
    c.x = (char)(int)rintf(v2[0]*i2); c.y = (char)(int)rintf(v2[1]*i2);
    c.z = (char)(int)rintf(v2[2]*i2); c.w = (char)(int)rintf(v2[3]*i2);
    d2[t] = c;
    c.x = (char)(int)rintf(v2[4]*i2); c.y = (char)(int)rintf(v2[5]*i2);
    c.z = (char)(int)rintf(v2[6]*i2); c.w = (char)(int)rintf(v2[7]*i2);
    d2[t + 256] = c;
    c.x = (char)(int)rintf(v3[0]*i3); c.y = (char)(int)rintf(v3[1]*i3);
    c.z = (char)(int)rintf(v3[2]*i3); c.w = (char)(int)rintf(v3[3]*i3);
    d3[t] = c;
    c.x = (char)(int)rintf(v3[4]*i3); c.y = (char)(int)rintf(v3[5]*i3);
    c.z = (char)(int)rintf(v3[6]*i3); c.w = (char)(int)rintf(v3[7]*i3);
    d3[t + 256] = c;

    if (t == 0) {
        g_xscale[row0 + 0] = m0 * (1.0f / 127.0f);
        g_xscale[row0 + 1] = m1 * (1.0f / 127.0f);
        g_xscale[row0 + 2] = m2 * (1.0f / 127.0f);
        g_xscale[row0 + 3] = m3 * (1.0f / 127.0f);
    }
}

// ---------------------------------------------------------------------------
// Kernel 2: int8 tensor-core GEMM via mma.sync.m16n8k32 with fused dequant.
// CTA tile 128x256, K staged 128B, 8 warps (2x4), warp tile 64x64,
// 4-stage cp.async pipeline.  Epilogue writes v = acc*x_scale*w_scale as f16.
// ---------------------------------------------------------------------------
#define BM  128
#define BN  256
#define BKB 128   // K-bytes per stage
#define NIT (K_DIM / BKB)   // 16
#define NSTAGE 4
#define A_BYTES (BM * BKB)                // 16 KB
#define B_BYTES (BN * BKB)                // 32 KB
#define STAGE_BYTES (A_BYTES + B_BYTES)   // 48 KB
#define SMEM_DYN (NSTAGE * STAGE_BYTES)   // 192 KB

__device__ __forceinline__ uint32_t smem_u32(const void* p) {
    uint32_t a;
    asm("{ .reg .u64 t; cvta.to.shared.u64 t, %1; cvt.u32.u64 %0, t; }" : "=r"(a) : "l"(p));
    return a;
}

// swizzled byte offset within a [rows x 128B] tile
__device__ __forceinline__ uint32_t swz(int row, int c) {
    return (uint32_t)(row * 128 + ((c ^ (row & 7)) << 4));
}

__device__ __forceinline__ void cp16(uint32_t saddr, const void* g) {
    asm volatile("cp.async.cg.shared.global [%0], [%1], 16;" :: "r"(saddr), "l"(g));
}

__device__ __forceinline__ void ldsm4(uint32_t* r, uint32_t addr) {
    asm volatile("ldmatrix.sync.aligned.m8n8.x4.shared.b16 {%0,%1,%2,%3}, [%4];"
                 : "=r"(r[0]), "=r"(r[1]), "=r"(r[2]), "=r"(r[3]) : "r"(addr));
}

__device__ __forceinline__ void mma_s8(int* c, const uint32_t* a, const uint32_t* b) {
    asm volatile(
        "mma.sync.aligned.m16n8k32.row.col.s32.s8.s8.s32 "
        "{%0,%1,%2,%3}, {%4,%5,%6,%7}, {%8,%9}, {%0,%1,%2,%3};"
        : "+r"(c[0]), "+r"(c[1]), "+r"(c[2]), "+r"(c[3])
        : "r"(a[0]), "r"(a[1]), "r"(a[2]), "r"(a[3]), "r"(b[0]), "r"(b[1]));
}

__global__ __launch_bounds__(256, 1) void gemm_kernel(const float* __restrict__ wscale) {
    extern __shared__ uint8_t smem[];

    const int tid  = threadIdx.x;
    const int wid  = tid >> 5;
    const int lane = tid & 31;
    const int wm   = wid >> 2;          // 0..1 -> m offset wm*64
    const int wn   = wid & 3;           // 0..3 -> n offset wn*64
    const int bm   = (int)blockIdx.y * BM;
    const int bn   = (int)blockIdx.x * BN;
    const uint32_t sbase = smem_u32(smem);

    int acc[4][8][4];
    #pragma unroll
    for (int i = 0; i < 4; i++)
        #pragma unroll
        for (int j = 0; j < 8; j++)
            #pragma unroll
            for (int r = 0; r < 4; r++) acc[i][j][r] = 0;

    // cooperative load of one stage: A 1024 + B 2048 chunks of 16B = 12/thread
    auto load_stage = [&](int st, int k0) {
        uint32_t sa = sbase + st * STAGE_BYTES;
        uint32_t sb = sa + A_BYTES;
        #pragma unroll
        for (int i = 0; i < 12; i++) {
            int idx = tid + i * 256;        // 0..3071
            if (idx < 1024) {
                int row = idx >> 3, c = idx & 7;
                cp16(sa + swz(row, c), g_xq + (size_t)(bm + row) * K_DIM + k0 + c * 16);
            } else {
                int j = idx - 1024;
                int row = j >> 3, c = j & 7;
                cp16(sb + swz(row, c), g_w + (size_t)(bn + row) * K_DIM + k0 + c * 16);
            }
        }
    };

    // prologue: 3 stages in flight
    load_stage(0, 0);
    asm volatile("cp.async.commit_group;" ::: "memory");
    load_stage(1, BKB);
    asm volatile("cp.async.commit_group;" ::: "memory");
    load_stage(2, 2 * BKB);
    asm volatile("cp.async.commit_group;" ::: "memory");

    const int lrow = lane & 15;         // ldmatrix row within 16
    const int lchk = lane >> 4;         // ldmatrix chunk select

    for (int it = 0; it < NIT; ++it) {
        asm volatile("cp.async.wait_group 2;" ::: "memory");
        __syncthreads();

        int nt = it + 3;
        if (nt < NIT) load_stage(nt % NSTAGE, nt * BKB);
        asm volatile("cp.async.commit_group;" ::: "memory");

        const int st = it % NSTAGE;
        const uint32_t sa = sbase + st * STAGE_BYTES;
        const uint32_t sb = sa + A_BYTES;

        #pragma unroll
        for (int ks = 0; ks < 4; ks++) {    // four k32 steps per 128B stage
            uint32_t a[4][4];
            #pragma unroll
            for (int i = 0; i < 4; i++) {
                int row = wm * 64 + i * 16 + lrow;
                ldsm4(a[i], sa + swz(row, ks * 2 + lchk));
            }
            uint32_t b[8][2];
            #pragma unroll
            for (int jj = 0; jj < 4; jj++) {
                uint32_t r[4];
                int row = wn * 64 + jj * 16 + lrow;
                ldsm4(r, sb + swz(row, ks * 2 + lchk));
                b[jj*2][0]   = r[0]; b[jj*2][1]   = r[2];
                b[jj*2+1][0] = r[1]; b[jj*2+1][1] = r[3];
            }
            #pragma unroll
            for (int i = 0; i < 4; i++)
                #pragma unroll
                for (int j = 0; j < 8; j++)
                    mma_s8(acc[i][j], a[i], b[j]);
        }
    }

    // epilogue: fused dequant, f16 streaming stores (no reuse until ln_out)
    #pragma unroll
    for (int i = 0; i < 4; i++) {
        int r0 = bm + wm * 64 + i * 16 + (lane >> 2);
        float st0 = g_xscale[r0];
        float st1 = g_xscale[r0 + 8];
        #pragma unroll
        for (int j = 0; j < 8; j++) {
            int col = bn + wn * 64 + j * 8 + (lane & 3) * 2;
            float w0 = __ldg(&wscale[col]);
            float w1 = __ldg(&wscale[col + 1]);
            __half2 h0 = __floats2half2_rn((float)acc[i][j][0] * st0 * w0,
                                           (float)acc[i][j][1] * st0 * w1);
            __half2 h1 = __floats2half2_rn((float)acc[i][j][2] * st1 * w0,
                                           (float)acc[i][j][3] * st1 * w1);
            __stcs((uint32_t*)(g_vh + (size_t)r0 * N_DIM + col),
                   *reinterpret_cast<uint32_t*>(&h0));
            __stcs((uint32_t*)(g_vh + (size_t)(r0 + 8) * N_DIM + col),
                   *reinterpret_cast<uint32_t*>(&h1));
        }
    }
}

// ---------------------------------------------------------------------------
// Kernel 3: output LayerNorm over the f16 dequantized GEMM result.
// 2 token rows per block; stats in f32.
// ---------------------------------------------------------------------------
__global__ __launch_bounds__(256) void ln_out_kernel(float* __restrict__ out) {
    __shared__ float sh[36];
    const int row0 = (int)blockIdx.x * 2;
    const int row1 = row0 + 1;
    const int t = threadIdx.x;

    const uint4* vr0 = (const uint4*)(g_vh + (size_t)row0 * N_DIM);
    const uint4* vr1 = (const uint4*)(g_vh + (size_t)row1 * N_DIM);

    uint4 p0 = __ldcs(&vr0[t]);    // 8 halves for row0
    uint4 p1 = __ldcs(&vr1[t]);    // 8 halves for row1

    float v0[8], v1[8];
    {
        float2 f;
        f = __half22float2(*reinterpret_cast<__half2*>(&p0.x)); v0[0]=f.x; v0[1]=f.y;
        f = __half22float2(*reinterpret_cast<__half2*>(&p0.y)); v0[2]=f.x; v0[3]=f.y;
        f = __half22float2(*reinterpret_cast<__half2*>(&p0.z)); v0[4]=f.x; v0[5]=f.y;
        f = __half22float2(*reinterpret_cast<__half2*>(&p0.w)); v0[6]=f.x; v0[7]=f.y;
        f = __half22float2(*reinterpret_cast<__half2*>(&p1.x)); v1[0]=f.x; v1[1]=f.y;
        f = __half22float2(*reinterpret_cast<__half2*>(&p1.y)); v1[2]=f.x; v1[3]=f.y;
        f = __half22float2(*reinterpret_cast<__half2*>(&p1.z)); v1[4]=f.x; v1[5]=f.y;
        f = __half22float2(*reinterpret_cast<__half2*>(&p1.w)); v1[6]=f.x; v1[7]=f.y;
    }

    float s0 = 0.f, ss0 = 0.f, s1 = 0.f, ss1 = 0.f;
    #pragma unroll
    for (int i = 0; i < 8; i++) {
        s0 += v0[i]; ss0 += v0[i]*v0[i];
        s1 += v1[i]; ss1 += v1[i]*v1[i];
    }
    block_reduce_sum4(s0, ss0, s1, ss1, sh);

    const float invn = 1.0f / (float)N_DIM;
    float mu0  = s0 * invn;
    float var0 = fmaxf(ss0 * invn - mu0 * mu0, 0.f);
    float rstd0 = rsqrtf(var0 + 1e-5f);
    float mu1  = s1 * invn;
    float var1 = fmaxf(ss1 * invn - mu1 * mu1, 0.f);
    float rstd1 = rsqrtf(var1 + 1e-5f);

    // out layout: thread t owns elements [8t..8t+7] of each row
    float4* d0 = (float4*)(out + (size_t)row0 * N_DIM) + 2 * t;
    float4* d1 = (float4*)(out + (size_t)row1 * N_DIM) + 2 * t;
    float4 o;
    o.x = (v0[0]-mu0)*rstd0; o.y = (v0[1]-mu0)*rstd0;
    o.z = (v0[2]-mu0)*rstd0; o.w = (v0[3]-mu0)*rstd0;
    __stcs(&d0[0], o);
    o.x = (v0[4]-mu0)*rstd0; o.y = (v0[5]-mu0)*rstd0;
    o.z = (v0[6]-mu0)*rstd0; o.w = (v0[7]-mu0)*rstd0;
    __stcs(&d0[1], o);
    o.x = (v1[0]-mu1)*rstd1; o.y = (v1[1]-mu1)*rstd1;
    o.z = (v1[2]-mu1)*rstd1; o.w = (v1[3]-mu1)*rstd1;
    __stcs(&d1[0], o);
    o.x = (v1[4]-mu1)*rstd1; o.y = (v1[5]-mu1)*rstd1;
    o.z = (v1[6]-mu1)*rstd1; o.w = (v1[7]-mu1)*rstd1;
    __stcs(&d1[1], o);
}

// ---------------------------------------------------------------------------
// Launch (3 kernels: ln_quant+pack fused, gemm+dequant fused, ln_out)
// ---------------------------------------------------------------------------
extern "C" void kernel_launch(void* const* d_in, const int* in_sizes, int n_in,
                              void* d_out, int out_size) {
    const float* x  = (const float*)d_in[0];          // [4,4096,2048] f32
    const int*   wt = (const int*)d_in[1];            // [2048,2048] i32 ternary
    const float* ws = (const float*)d_in[2];          // [2048] f32
    float* out = (float*)d_out;                       // [4,4096,2048] f32

    cudaFuncSetAttribute(gemm_kernel, cudaFuncAttributeMaxDynamicSharedMemorySize, SMEM_DYN);

    ln_quant_kernel<<<LNQ_BLOCKS + PACK_BLOCKS, 256>>>(x, wt);
    dim3 grid(N_DIM / BN, M_TOK / BM);                // (8, 128) = 1024 CTAs
    gemm_kernel<<<grid, 256, SMEM_DYN>>>(ws);
    ln_out_kernel<<<M_TOK / 2, 256>>>(out);
}

// round 14
// speedup vs baseline: 1.0203x; 1.0174x over previous
#include <cuda_runtime.h>
#include <cuda_fp16.h>
#include <cstdint>

#define M_TOK 16384   // B*S tokens
#define K_DIM 2048    // DIN
#define N_DIM 2048    // DOUT

// ---------------------------------------------------------------------------
// Scratch (__device__ globals; no allocations allowed)
// ---------------------------------------------------------------------------
__device__ int8_t g_xq[(size_t)M_TOK * K_DIM];      // 32 MB quantized activations
__device__ float  g_xscale[M_TOK];                  // per-token scale
__device__ int8_t g_w[(size_t)N_DIM * K_DIM];       // 4 MB ternary weights as int8
__device__ __half g_vh[(size_t)M_TOK * N_DIM];      // 64 MB dequantized GEMM output (f16)

// ---------------------------------------------------------------------------
// Warp reductions (no barriers)
// ---------------------------------------------------------------------------
__device__ __forceinline__ void warp_reduce_sum2(float& a, float& b) {
    #pragma unroll
    for (int o = 16; o > 0; o >>= 1) {
        a += __shfl_xor_sync(0xFFFFFFFFu, a, o);
        b += __shfl_xor_sync(0xFFFFFFFFu, b, o);
    }
}
__device__ __forceinline__ void warp_reduce_max(float& a) {
    #pragma unroll
    for (int o = 16; o > 0; o >>= 1)
        a = fmaxf(a, __shfl_xor_sync(0xFFFFFFFFu, a, o));
}

// ---------------------------------------------------------------------------
// Kernel 1: fused input LayerNorm + per-token int8 absmax quantization.
// WARP-PER-ROW: one warp owns one token row (64 elems/lane), zero barriers.
// Blocks [LNQ_BLOCKS ..) repack the ternary weights.
// ---------------------------------------------------------------------------
#define LNQ_BLOCKS (M_TOK / 8)                        // 2048 (8 warps/block)
#define PACK_BLOCKS 2048
__global__ __launch_bounds__(256) void ln_quant_kernel(const float* __restrict__ x,
                                                       const int* __restrict__ wt) {
    const int t = threadIdx.x;

    if (blockIdx.x >= LNQ_BLOCKS) {
        // weight repack role: int32 ternary -> int8
        int base = (int)(blockIdx.x - LNQ_BLOCKS) * 512 + t * 2;
        #pragma unroll
        for (int l = 0; l < 2; l++) {
            int idx = base + l;
            int4 v = __ldcs(&((const int4*)wt)[idx]);
            char4 c;
            c.x = (char)v.x; c.y = (char)v.y; c.z = (char)v.z; c.w = (char)v.w;
            ((char4*)g_w)[idx] = c;
        }
        return;
    }

    const int wid  = t >> 5;
    const int lane = t & 31;
    const int row  = (int)blockIdx.x * 8 + wid;
    const float4* xr = (const float4*)(x + (size_t)row * K_DIM);

    // 16 float4 per lane, stride 32 (coalesced), all issued up front
    float4 v[16];
    #pragma unroll
    for (int k = 0; k < 16; k++)
        v[k] = __ldcs(&xr[lane + 32 * k]);

    float s = 0.f, ss = 0.f;
    #pragma unroll
    for (int k = 0; k < 16; k++) {
        s  += v[k].x + v[k].y + v[k].z + v[k].w;
        ss += v[k].x*v[k].x + v[k].y*v[k].y + v[k].z*v[k].z + v[k].w*v[k].w;
    }
    warp_reduce_sum2(s, ss);

    const float invn = 1.0f / (float)K_DIM;
    float mu   = s * invn;
    float rstd = rsqrtf(fmaxf(ss * invn - mu * mu, 0.f) + 1e-5f);

    float amax = 0.f;
    #pragma unroll
    for (int k = 0; k < 16; k++) {
        v[k].x = (v[k].x - mu) * rstd;
        v[k].y = (v[k].y - mu) * rstd;
        v[k].z = (v[k].z - mu) * rstd;
        v[k].w = (v[k].w - mu) * rstd;
        amax = fmaxf(amax, fmaxf(fmaxf(fabsf(v[k].x), fabsf(v[k].y)),
                                 fmaxf(fabsf(v[k].z), fabsf(v[k].w))));
    }
    warp_reduce_max(amax);
    amax = fmaxf(amax, 1e-5f);
    float inv = 127.0f / amax;

    char4* dst = (char4*)(g_xq + (size_t)row * K_DIM);
    #pragma unroll
    for (int k = 0; k < 16; k++) {
        char4 c;
        c.x = (char)(int)rintf(v[k].x * inv);
        c.y = (char)(int)rintf(v[k].y * inv);
        c.z = (char)(int)rintf(v[k].z * inv);
        c.w = (char)(int)rintf(v[k].w * inv);
        dst[lane + 32 * k] = c;
    }
    if (lane == 0) g_xscale[row] = amax * (1.0f / 127.0f);
}

// ---------------------------------------------------------------------------
// Kernel 2: int8 tensor-core GEMM via mma.sync.m16n8k32 with fused dequant.
// CTA tile 128x256, K staged 128B, 8 warps (2x4), warp tile 64x64,
// 4-stage cp.async pipeline.  Epilogue writes v = acc*x_scale*w_scale as f16.
// ---------------------------------------------------------------------------
#define BM  128
#define BN  256
#define BKB 128   // K-bytes per stage
#define NIT (K_DIM / BKB)   // 16
#define NSTAGE 4
#define A_BYTES (BM * BKB)                // 16 KB
#define B_BYTES (BN * BKB)                // 32 KB
#define STAGE_BYTES (A_BYTES + B_BYTES)   // 48 KB
#define SMEM_DYN (NSTAGE * STAGE_BYTES)   // 192 KB

__device__ __forceinline__ uint32_t smem_u32(const void* p) {
    uint32_t a;
    asm("{ .reg .u64 t; cvta.to.shared.u64 t, %1; cvt.u32.u64 %0, t; }" : "=r"(a) : "l"(p));
    return a;
}

// swizzled byte offset within a [rows x 128B] tile
__device__ __forceinline__ uint32_t swz(int row, int c) {
    return (uint32_t)(row * 128 + ((c ^ (row & 7)) << 4));
}

__device__ __forceinline__ void cp16(uint32_t saddr, const void* g) {
    asm volatile("cp.async.cg.shared.global [%0], [%1], 16;" :: "r"(saddr), "l"(g));
}

__device__ __forceinline__ void ldsm4(uint32_t* r, uint32_t addr) {
    asm volatile("ldmatrix.sync.aligned.m8n8.x4.shared.b16 {%0,%1,%2,%3}, [%4];"
                 : "=r"(r[0]), "=r"(r[1]), "=r"(r[2]), "=r"(r[3]) : "r"(addr));
}

__device__ __forceinline__ void mma_s8(int* c, const uint32_t* a, const uint32_t* b) {
    asm volatile(
        "mma.sync.aligned.m16n8k32.row.col.s32.s8.s8.s32 "
        "{%0,%1,%2,%3}, {%4,%5,%6,%7}, {%8,%9}, {%0,%1,%2,%3};"
        : "+r"(c[0]), "+r"(c[1]), "+r"(c[2]), "+r"(c[3])
        : "r"(a[0]), "r"(a[1]), "r"(a[2]), "r"(a[3]), "r"(b[0]), "r"(b[1]));
}

__global__ __launch_bounds__(256, 1) void gemm_kernel(const float* __restrict__ wscale) {
    extern __shared__ uint8_t smem[];

    const int tid  = threadIdx.x;
    const int wid  = tid >> 5;
    const int lane = tid & 31;
    const int wm   = wid >> 2;          // 0..1 -> m offset wm*64
    const int wn   = wid & 3;           // 0..3 -> n offset wn*64
    const int bm   = (int)blockIdx.y * BM;
    const int bn   = (int)blockIdx.x * BN;
    const uint32_t sbase = smem_u32(smem);

    int acc[4][8][4];
    #pragma unroll
    for (int i = 0; i < 4; i++)
        #pragma unroll
        for (int j = 0; j < 8; j++)
            #pragma unroll
            for (int r = 0; r < 4; r++) acc[i][j][r] = 0;

    // cooperative load of one stage: A 1024 + B 2048 chunks of 16B = 12/thread
    auto load_stage = [&](int st, int k0) {
        uint32_t sa = sbase + st * STAGE_BYTES;
        uint32_t sb = sa + A_BYTES;
        #pragma unroll
        for (int i = 0; i < 12; i++) {
            int idx = tid + i * 256;        // 0..3071
            if (idx < 1024) {
                int row = idx >> 3, c = idx & 7;
                cp16(sa + swz(row, c), g_xq + (size_t)(bm + row) * K_DIM + k0 + c * 16);
            } else {
                int j = idx - 1024;
                int row = j >> 3, c = j & 7;
                cp16(sb + swz(row, c), g_w + (size_t)(bn + row) * K_DIM + k0 + c * 16);
            }
        }
    };

    // prologue: 3 stages in flight
    load_stage(0, 0);
    asm volatile("cp.async.commit_group;" ::: "memory");
    load_stage(1, BKB);
    asm volatile("cp.async.commit_group;" ::: "memory");
    load_stage(2, 2 * BKB);
    asm volatile("cp.async.commit_group;" ::: "memory");

    const int lrow = lane & 15;         // ldmatrix row within 16
    const int lchk = lane >> 4;         // ldmatrix chunk select

    for (int it = 0; it < NIT; ++it) {
        asm volatile("cp.async.wait_group 2;" ::: "memory");
        __syncthreads();

        int nt = it + 3;
        if (nt < NIT) load_stage(nt % NSTAGE, nt * BKB);
        asm volatile("cp.async.commit_group;" ::: "memory");

        const int st = it % NSTAGE;
        const uint32_t sa = sbase + st * STAGE_BYTES;
        const uint32_t sb = sa + A_BYTES;

        #pragma unroll
        for (int ks = 0; ks < 4; ks++) {    // four k32 steps per 128B stage
            uint32_t a[4][4];
            #pragma unroll
            for (int i = 0; i < 4; i++) {
                int row = wm * 64 + i * 16 + lrow;
                ldsm4(a[i], sa + swz(row, ks * 2 + lchk));
            }
            uint32_t b[8][2];
            #pragma unroll
            for (int jj = 0; jj < 4; jj++) {
                uint32_t r[4];
                int row = wn * 64 + jj * 16 + lrow;
                ldsm4(r, sb + swz(row, ks * 2 + lchk));
                b[jj*2][0]   = r[0]; b[jj*2][1]   = r[2];
                b[jj*2+1][0] = r[1]; b[jj*2+1][1] = r[3];
            }
            #pragma unroll
            for (int i = 0; i < 4; i++)
                #pragma unroll
                for (int j = 0; j < 8; j++)
                    mma_s8(acc[i][j], a[i], b[j]);
        }
    }

    // epilogue: fused dequant, f16 streaming stores (no reuse until ln_out)
    #pragma unroll
    for (int i = 0; i < 4; i++) {
        int r0 = bm + wm * 64 + i * 16 + (lane >> 2);
        float st0 = g_xscale[r0];
        float st1 = g_xscale[r0 + 8];
        #pragma unroll
        for (int j = 0; j < 8; j++) {
            int col = bn + wn * 64 + j * 8 + (lane & 3) * 2;
            float w0 = __ldg(&wscale[col]);
            float w1 = __ldg(&wscale[col + 1]);
            __half2 h0 = __floats2half2_rn((float)acc[i][j][0] * st0 * w0,
                                           (float)acc[i][j][1] * st0 * w1);
            __half2 h1 = __floats2half2_rn((float)acc[i][j][2] * st1 * w0,
                                           (float)acc[i][j][3] * st1 * w1);
            __stcs((uint32_t*)(g_vh + (size_t)r0 * N_DIM + col),
                   *reinterpret_cast<uint32_t*>(&h0));
            __stcs((uint32_t*)(g_vh + (size_t)(r0 + 8) * N_DIM + col),
                   *reinterpret_cast<uint32_t*>(&h1));
        }
    }
}

// ---------------------------------------------------------------------------
// Kernel 3: output LayerNorm over the f16 dequantized GEMM result.
// WARP-PER-ROW: one warp owns one token row (64 halves/lane), zero barriers.
// Stats in f32.
// ---------------------------------------------------------------------------
__global__ __launch_bounds__(256) void ln_out_kernel(float* __restrict__ out) {
    const int t    = threadIdx.x;
    const int wid  = t >> 5;
    const int lane = t & 31;
    const int row  = (int)blockIdx.x * 8 + wid;

    const uint4* vr = (const uint4*)(g_vh + (size_t)row * N_DIM);   // 256 uint4/row

    uint4 p[8];
    #pragma unroll
    for (int k = 0; k < 8; k++)
        p[k] = __ldcs(&vr[lane + 32 * k]);

    float s = 0.f, ss = 0.f;
    #pragma unroll
    for (int k = 0; k < 8; k++) {
        float2 f0 = __half22float2(*reinterpret_cast<__half2*>(&p[k].x));
        float2 f1 = __half22float2(*reinterpret_cast<__half2*>(&p[k].y));
        float2 f2 = __half22float2(*reinterpret_cast<__half2*>(&p[k].z));
        float2 f3 = __half22float2(*reinterpret_cast<__half2*>(&p[k].w));
        s  += f0.x + f0.y + f1.x + f1.y + f2.x + f2.y + f3.x + f3.y;
        ss += f0.x*f0.x + f0.y*f0.y + f1.x*f1.x + f1.y*f1.y
            + f2.x*f2.x + f2.y*f2.y + f3.x*f3.x + f3.y*f3.y;
    }
    warp_reduce_sum2(s, ss);

    const float invn = 1.0f / (float)N_DIM;
    float mu   = s * invn;
    float rstd = rsqrtf(fmaxf(ss * invn - mu * mu, 0.f) + 1e-5f);

    // normalize + store: uint4 k covers halves [(lane+32k)*8 .. +7]
    float4* dst = (float4*)(out + (size_t)row * N_DIM);
    #pragma unroll
    for (int k = 0; k < 8; k++) {
        int f4i = 2 * (lane + 32 * k);
        float2 f0 = __half22float2(*reinterpret_cast<__half2*>(&p[k].x));
        float2 f1 = __half22float2(*reinterpret_cast<__half2*>(&p[k].y));
        float2 f2 = __half22float2(*reinterpret_cast<__half2*>(&p[k].z));
        float2 f3 = __half22float2(*reinterpret_cast<__half2*>(&p[k].w));
        float4 o;
        o.x = (f0.x - mu) * rstd; o.y = (f0.y - mu) * rstd;
        o.z = (f1.x - mu) * rstd; o.w = (f1.y - mu) * rstd;
        __stcs(&dst[f4i], o);
        o.x = (f2.x - mu) * rstd; o.y = (f2.y - mu) * rstd;
        o.z = (f3.x - mu) * rstd; o.w = (f3.y - mu) * rstd;
        __stcs(&dst[f4i + 1], o);
    }
}

// ---------------------------------------------------------------------------
// Launch (3 kernels: ln_quant+pack fused, gemm+dequant fused, ln_out)
// ---------------------------------------------------------------------------
extern "C" void kernel_launch(void* const* d_in, const int* in_sizes, int n_in,
                              void* d_out, int out_size) {
    const float* x  = (const float*)d_in[0];          // [4,4096,2048] f32
    const int*   wt = (const int*)d_in[1];            // [2048,2048] i32 ternary
    const float* ws = (const float*)d_in[2];          // [2048] f32
    float* out = (float*)d_out;                       // [4,4096,2048] f32

    cudaFuncSetAttribute(gemm_kernel, cudaFuncAttributeMaxDynamicSharedMemorySize, SMEM_DYN);

    ln_quant_kernel<<<LNQ_BLOCKS + PACK_BLOCKS, 256>>>(x, wt);
    dim3 grid(N_DIM / BN, M_TOK / BM);                // (8, 128) = 1024 CTAs
    gemm_kernel<<<grid, 256, SMEM_DYN>>>(ws);
    ln_out_kernel<<<M_TOK / 8, 256>>>(out);
}

// round 15
// speedup vs baseline: 1.0265x; 1.0061x over previous
#include <cuda_runtime.h>
#include <cuda_fp16.h>
#include <cstdint>

#define M_TOK 16384   // B*S tokens
#define K_DIM 2048    // DIN
#define N_DIM 2048    // DOUT

// ---------------------------------------------------------------------------
// Scratch (__device__ globals; no allocations allowed)
// ---------------------------------------------------------------------------
__device__ int8_t g_xq[(size_t)M_TOK * K_DIM];      // 32 MB quantized activations
__device__ float  g_xscale[M_TOK];                  // per-token scale
__device__ int8_t g_w[(size_t)N_DIM * K_DIM];       // 4 MB ternary weights as int8
__device__ __half g_vh[(size_t)M_TOK * N_DIM];      // 64 MB dequantized GEMM output (f16)

// ---------------------------------------------------------------------------
// Warp reductions (no barriers)
// ---------------------------------------------------------------------------
__device__ __forceinline__ void warp_reduce_sum2(float& a, float& b) {
    #pragma unroll
    for (int o = 16; o > 0; o >>= 1) {
        a += __shfl_xor_sync(0xFFFFFFFFu, a, o);
        b += __shfl_xor_sync(0xFFFFFFFFu, b, o);
    }
}
__device__ __forceinline__ void warp_reduce_max(float& a) {
    #pragma unroll
    for (int o = 16; o > 0; o >>= 1)
        a = fmaxf(a, __shfl_xor_sync(0xFFFFFFFFu, a, o));
}

// ---------------------------------------------------------------------------
// Kernel 1: fused input LayerNorm + per-token int8 absmax quantization.
// WARP-PER-ROW: one warp owns one token row (64 elems/lane), zero barriers.
// Blocks [LNQ_BLOCKS ..) repack the ternary weights.
// ---------------------------------------------------------------------------
#define LNQ_BLOCKS (M_TOK / 8)                        // 2048 (8 warps/block)
#define PACK_BLOCKS 2048
__global__ __launch_bounds__(256) void ln_quant_kernel(const float* __restrict__ x,
                                                       const int* __restrict__ wt) {
    const int t = threadIdx.x;

    if (blockIdx.x >= LNQ_BLOCKS) {
        // weight repack role: int32 ternary -> int8
        int base = (int)(blockIdx.x - LNQ_BLOCKS) * 512 + t * 2;
        #pragma unroll
        for (int l = 0; l < 2; l++) {
            int idx = base + l;
            int4 v = __ldcs(&((const int4*)wt)[idx]);
            char4 c;
            c.x = (char)v.x; c.y = (char)v.y; c.z = (char)v.z; c.w = (char)v.w;
            ((char4*)g_w)[idx] = c;
        }
        return;
    }

    const int wid  = t >> 5;
    const int lane = t & 31;
    const int row  = (int)blockIdx.x * 8 + wid;
    const float4* xr = (const float4*)(x + (size_t)row * K_DIM);

    // 16 float4 per lane, stride 32 (coalesced), all issued up front
    float4 v[16];
    #pragma unroll
    for (int k = 0; k < 16; k++)
        v[k] = __ldcs(&xr[lane + 32 * k]);

    float s = 0.f, ss = 0.f;
    #pragma unroll
    for (int k = 0; k < 16; k++) {
        s  += v[k].x + v[k].y + v[k].z + v[k].w;
        ss += v[k].x*v[k].x + v[k].y*v[k].y + v[k].z*v[k].z + v[k].w*v[k].w;
    }
    warp_reduce_sum2(s, ss);

    const float invn = 1.0f / (float)K_DIM;
    float mu   = s * invn;
    float rstd = rsqrtf(fmaxf(ss * invn - mu * mu, 0.f) + 1e-5f);

    float amax = 0.f;
    #pragma unroll
    for (int k = 0; k < 16; k++) {
        v[k].x = (v[k].x - mu) * rstd;
        v[k].y = (v[k].y - mu) * rstd;
        v[k].z = (v[k].z - mu) * rstd;
        v[k].w = (v[k].w - mu) * rstd;
        amax = fmaxf(amax, fmaxf(fmaxf(fabsf(v[k].x), fabsf(v[k].y)),
                                 fmaxf(fabsf(v[k].z), fabsf(v[k].w))));
    }
    warp_reduce_max(amax);
    amax = fmaxf(amax, 1e-5f);
    float inv = 127.0f / amax;

    char4* dst = (char4*)(g_xq + (size_t)row * K_DIM);
    #pragma unroll
    for (int k = 0; k < 16; k++) {
        char4 c;
        c.x = (char)(int)rintf(v[k].x * inv);
        c.y = (char)(int)rintf(v[k].y * inv);
        c.z = (char)(int)rintf(v[k].z * inv);
        c.w = (char)(int)rintf(v[k].w * inv);
        dst[lane + 32 * k] = c;
    }
    if (lane == 0) g_xscale[row] = amax * (1.0f / 127.0f);
}

// ---------------------------------------------------------------------------
// Kernel 2: PERSISTENT int8 tensor-core GEMM via mma.sync.m16n8k32, fused
// dequant.  148 CTAs; each loops over tiles (stride 148).  Mainloop iters
// 13..15 prefetch the NEXT tile's stages 0..2, so prologue+epilogue overlap
// the MMA tail — only the very first prologue is exposed.
// ---------------------------------------------------------------------------
#define BM  128
#define BN  256
#define BKB 128   // K-bytes per stage
#define NIT (K_DIM / BKB)   // 16
#define NSTAGE 4
#define A_BYTES (BM * BKB)                // 16 KB
#define B_BYTES (BN * BKB)                // 32 KB
#define STAGE_BYTES (A_BYTES + B_BYTES)   // 48 KB
#define SMEM_DYN (NSTAGE * STAGE_BYTES)   // 192 KB
#define NTILES ((M_TOK / BM) * (N_DIM / BN))   // 1024
#define GRIDP 148

__device__ __forceinline__ uint32_t smem_u32(const void* p) {
    uint32_t a;
    asm("{ .reg .u64 t; cvta.to.shared.u64 t, %1; cvt.u32.u64 %0, t; }" : "=r"(a) : "l"(p));
    return a;
}

// swizzled byte offset within a [rows x 128B] tile
__device__ __forceinline__ uint32_t swz(int row, int c) {
    return (uint32_t)(row * 128 + ((c ^ (row & 7)) << 4));
}

__device__ __forceinline__ void cp16(uint32_t saddr, const void* g) {
    asm volatile("cp.async.cg.shared.global [%0], [%1], 16;" :: "r"(saddr), "l"(g));
}

__device__ __forceinline__ void ldsm4(uint32_t* r, uint32_t addr) {
    asm volatile("ldmatrix.sync.aligned.m8n8.x4.shared.b16 {%0,%1,%2,%3}, [%4];"
                 : "=r"(r[0]), "=r"(r[1]), "=r"(r[2]), "=r"(r[3]) : "r"(addr));
}

__device__ __forceinline__ void mma_s8(int* c, const uint32_t* a, const uint32_t* b) {
    asm volatile(
        "mma.sync.aligned.m16n8k32.row.col.s32.s8.s8.s32 "
        "{%0,%1,%2,%3}, {%4,%5,%6,%7}, {%8,%9}, {%0,%1,%2,%3};"
        : "+r"(c[0]), "+r"(c[1]), "+r"(c[2]), "+r"(c[3])
        : "r"(a[0]), "r"(a[1]), "r"(a[2]), "r"(a[3]), "r"(b[0]), "r"(b[1]));
}

__global__ __launch_bounds__(256, 1) void gemm_kernel(const float* __restrict__ wscale) {
    extern __shared__ uint8_t smem[];

    const int tid  = threadIdx.x;
    const int wid  = tid >> 5;
    const int lane = tid & 31;
    const int wm   = wid >> 2;          // 0..1 -> m offset wm*64
    const int wn   = wid & 3;           // 0..3 -> n offset wn*64
    const uint32_t sbase = smem_u32(smem);

    // cooperative load of one stage: A 1024 + B 2048 chunks of 16B = 12/thread
    auto load_stage = [&](int st, int bm, int bn, int k0) {
        uint32_t sa = sbase + st * STAGE_BYTES;
        uint32_t sb = sa + A_BYTES;
        #pragma unroll
        for (int i = 0; i < 12; i++) {
            int idx = tid + i * 256;        // 0..3071
            if (idx < 1024) {
                int row = idx >> 3, c = idx & 7;
                cp16(sa + swz(row, c), g_xq + (size_t)(bm + row) * K_DIM + k0 + c * 16);
            } else {
                int j = idx - 1024;
                int row = j >> 3, c = j & 7;
                cp16(sb + swz(row, c), g_w + (size_t)(bn + row) * K_DIM + k0 + c * 16);
            }
        }
    };

    const int lrow = lane & 15;         // ldmatrix row within 16
    const int lchk = lane >> 4;         // ldmatrix chunk select

    int tile = (int)blockIdx.x;

    // first-tile prologue: 3 stages in flight
    {
        int bm = (tile >> 3) * BM, bn = (tile & 7) * BN;
        load_stage(0, bm, bn, 0);
        asm volatile("cp.async.commit_group;" ::: "memory");
        load_stage(1, bm, bn, BKB);
        asm volatile("cp.async.commit_group;" ::: "memory");
        load_stage(2, bm, bn, 2 * BKB);
        asm volatile("cp.async.commit_group;" ::: "memory");
    }

    for (; tile < NTILES; tile += GRIDP) {
        const int bm = (tile >> 3) * BM;
        const int bn = (tile & 7) * BN;
        const int tile2 = tile + GRIDP;
        const bool has_next = tile2 < NTILES;
        const int bm2 = has_next ? (tile2 >> 3) * BM : 0;
        const int bn2 = has_next ? (tile2 & 7) * BN : 0;

        int acc[4][8][4];
        #pragma unroll
        for (int i = 0; i < 4; i++)
            #pragma unroll
            for (int j = 0; j < 8; j++)
                #pragma unroll
                for (int r = 0; r < 4; r++) acc[i][j][r] = 0;

        for (int it = 0; it < NIT; ++it) {
            asm volatile("cp.async.wait_group 2;" ::: "memory");
            __syncthreads();

            // load this tile's stage nt, or prefetch next tile's stage nt-16
            int nt = it + 3;
            if (nt < NIT) {
                load_stage(nt % NSTAGE, bm, bn, nt * BKB);
            } else if (has_next) {
                load_stage(nt % NSTAGE, bm2, bn2, (nt - NIT) * BKB);
            }
            asm volatile("cp.async.commit_group;" ::: "memory");

            const int st = it % NSTAGE;
            const uint32_t sa = sbase + st * STAGE_BYTES;
            const uint32_t sb = sa + A_BYTES;

            #pragma unroll
            for (int ks = 0; ks < 4; ks++) {    // four k32 steps per 128B stage
                uint32_t a[4][4];
                #pragma unroll
                for (int i = 0; i < 4; i++) {
                    int row = wm * 64 + i * 16 + lrow;
                    ldsm4(a[i], sa + swz(row, ks * 2 + lchk));
                }
                uint32_t b[8][2];
                #pragma unroll
                for (int jj = 0; jj < 4; jj++) {
                    uint32_t r[4];
                    int row = wn * 64 + jj * 16 + lrow;
                    ldsm4(r, sb + swz(row, ks * 2 + lchk));
                    b[jj*2][0]   = r[0]; b[jj*2][1]   = r[2];
                    b[jj*2+1][0] = r[1]; b[jj*2+1][1] = r[3];
                }
                #pragma unroll
                for (int i = 0; i < 4; i++)
                    #pragma unroll
                    for (int j = 0; j < 8; j++)
                        mma_s8(acc[i][j], a[i], b[j]);
            }
        }

        // epilogue (next tile's stages 0..2 already streaming in)
        #pragma unroll
        for (int i = 0; i < 4; i++) {
            int r0 = bm + wm * 64 + i * 16 + (lane >> 2);
            float st0 = g_xscale[r0];
            float st1 = g_xscale[r0 + 8];
            #pragma unroll
            for (int j = 0; j < 8; j++) {
                int col = bn + wn * 64 + j * 8 + (lane & 3) * 2;
                float w0 = __ldg(&wscale[col]);
                float w1 = __ldg(&wscale[col + 1]);
                __half2 h0 = __floats2half2_rn((float)acc[i][j][0] * st0 * w0,
                                               (float)acc[i][j][1] * st0 * w1);
                __half2 h1 = __floats2half2_rn((float)acc[i][j][2] * st1 * w0,
                                               (float)acc[i][j][3] * st1 * w1);
                __stcs((uint32_t*)(g_vh + (size_t)r0 * N_DIM + col),
                       *reinterpret_cast<uint32_t*>(&h0));
                __stcs((uint32_t*)(g_vh + (size_t)(r0 + 8) * N_DIM + col),
                       *reinterpret_cast<uint32_t*>(&h1));
            }
        }
    }
}

// ---------------------------------------------------------------------------
// Kernel 3: output LayerNorm over the f16 dequantized GEMM result.
// WARP-PER-ROW: one warp owns one token row (64 halves/lane), zero barriers.
// Stats in f32.
// ---------------------------------------------------------------------------
__global__ __launch_bounds__(256) void ln_out_kernel(float* __restrict__ out) {
    const int t    = threadIdx.x;
    const int wid  = t >> 5;
    const int lane = t & 31;
    const int row  = (int)blockIdx.x * 8 + wid;

    const uint4* vr = (const uint4*)(g_vh + (size_t)row * N_DIM);   // 256 uint4/row

    uint4 p[8];
    #pragma unroll
    for (int k = 0; k < 8; k++)
        p[k] = __ldcs(&vr[lane + 32 * k]);

    float s = 0.f, ss = 0.f;
    #pragma unroll
    for (int k = 0; k < 8; k++) {
        float2 f0 = __half22float2(*reinterpret_cast<__half2*>(&p[k].x));
        float2 f1 = __half22float2(*reinterpret_cast<__half2*>(&p[k].y));
        float2 f2 = __half22float2(*reinterpret_cast<__half2*>(&p[k].z));
        float2 f3 = __half22float2(*reinterpret_cast<__half2*>(&p[k].w));
        s  += f0.x + f0.y + f1.x + f1.y + f2.x + f2.y + f3.x + f3.y;
        ss += f0.x*f0.x + f0.y*f0.y + f1.x*f1.x + f1.y*f1.y
            + f2.x*f2.x + f2.y*f2.y + f3.x*f3.x + f3.y*f3.y;
    }
    warp_reduce_sum2(s, ss);

    const float invn = 1.0f / (float)N_DIM;
    float mu   = s * invn;
    float rstd = rsqrtf(fmaxf(ss * invn - mu * mu, 0.f) + 1e-5f);

    // normalize + store: uint4 k covers halves [(lane+32k)*8 .. +7]
    float4* dst = (float4*)(out + (size_t)row * N_DIM);
    #pragma unroll
    for (int k = 0; k < 8; k++) {
        int f4i = 2 * (lane + 32 * k);
        float2 f0 = __half22float2(*reinterpret_cast<__half2*>(&p[k].x));
        float2 f1 = __half22float2(*reinterpret_cast<__half2*>(&p[k].y));
        float2 f2 = __half22float2(*reinterpret_cast<__half2*>(&p[k].z));
        float2 f3 = __half22float2(*reinterpret_cast<__half2*>(&p[k].w));
        float4 o;
        o.x = (f0.x - mu) * rstd; o.y = (f0.y - mu) * rstd;
        o.z = (f1.x - mu) * rstd; o.w = (f1.y - mu) * rstd;
        __stcs(&dst[f4i], o);
        o.x = (f2.x - mu) * rstd; o.y = (f2.y - mu) * rstd;
        o.z = (f3.x - mu) * rstd; o.w = (f3.y - mu) * rstd;
        __stcs(&dst[f4i + 1], o);
    }
}

// ---------------------------------------------------------------------------
// Launch (3 kernels: ln_quant+pack fused, persistent gemm+dequant, ln_out)
// ---------------------------------------------------------------------------
extern "C" void kernel_launch(void* const* d_in, const int* in_sizes, int n_in,
                              void* d_out, int out_size) {
    const float* x  = (const float*)d_in[0];          // [4,4096,2048] f32
    const int*   wt = (const int*)d_in[1];            // [2048,2048] i32 ternary
    const float* ws = (const float*)d_in[2];          // [2048] f32
    float* out = (float*)d_out;                       // [4,4096,2048] f32

    cudaFuncSetAttribute(gemm_kernel, cudaFuncAttributeMaxDynamicSharedMemorySize, SMEM_DYN);

    ln_quant_kernel<<<LNQ_BLOCKS + PACK_BLOCKS, 256>>>(x, wt);
    gemm_kernel<<<GRIDP, 256, SMEM_DYN>>>(ws);
    ln_out_kernel<<<M_TOK / 8, 256>>>(out);
}

// round 17
// speedup vs baseline: 1.0340x; 1.0073x over previous
#include <cuda_runtime.h>
#include <cuda_fp16.h>
#include <cstdint>

#define M_TOK 16384   // B*S tokens
#define K_DIM 2048    // DIN
#define N_DIM 2048    // DOUT

// ---------------------------------------------------------------------------
// Scratch (__device__ globals; no allocations allowed)
// ---------------------------------------------------------------------------
__device__ int8_t g_xq[(size_t)M_TOK * K_DIM];      // 32 MB quantized activations
__device__ float  g_xscale[M_TOK];                  // per-token scale
__device__ int8_t g_w[(size_t)N_DIM * K_DIM];       // 4 MB ternary weights as int8
__device__ __half g_vh[(size_t)M_TOK * N_DIM];      // 64 MB dequantized GEMM output (f16)

// ---------------------------------------------------------------------------
// Warp reductions (no barriers)
// ---------------------------------------------------------------------------
__device__ __forceinline__ void warp_reduce_sum2(float& a, float& b) {
    #pragma unroll
    for (int o = 16; o > 0; o >>= 1) {
        a += __shfl_xor_sync(0xFFFFFFFFu, a, o);
        b += __shfl_xor_sync(0xFFFFFFFFu, b, o);
    }
}
__device__ __forceinline__ void warp_reduce_max(float& a) {
    #pragma unroll
    for (int o = 16; o > 0; o >>= 1)
        a = fmaxf(a, __shfl_xor_sync(0xFFFFFFFFu, a, o));
}

// ---------------------------------------------------------------------------
// Kernel 1: fused input LayerNorm + per-token int8 absmax quantization.
// 2 WARPS PER ROW (64 threads, 8 float4/lane): halves register payload vs.
// warp-per-row -> ~2x occupancy.  Cross-warp reduction via 8-slot smem +
// named barrier scoped to the warp pair (no block-wide sync).
// Blocks [LNQ_BLOCKS ..) repack the ternary weights.
// ---------------------------------------------------------------------------
#define LNQ_BLOCKS (M_TOK / 4)                        // 4096 (4 rows/block)
#define PACK_BLOCKS 2048
__global__ __launch_bounds__(256) void ln_quant_kernel(const float* __restrict__ x,
                                                       const int* __restrict__ wt) {
    const int t = threadIdx.x;

    if (blockIdx.x >= LNQ_BLOCKS) {
        // weight repack role: int32 ternary -> int8
        int base = (int)(blockIdx.x - LNQ_BLOCKS) * 512 + t * 2;
        #pragma unroll
        for (int l = 0; l < 2; l++) {
            int idx = base + l;
            int4 v = __ldcs(&((const int4*)wt)[idx]);
            char4 c;
            c.x = (char)v.x; c.y = (char)v.y; c.z = (char)v.z; c.w = (char)v.w;
            ((char4*)g_w)[idx] = c;
        }
        return;
    }

    __shared__ float red[16];                 // [warp] sum / +8: ssq  (reused for max)
    const int warp  = t >> 5;                 // 0..7
    const int sub   = t >> 6;                 // row group 0..3
    const int l64   = t & 63;                 // lane within row group
    const int row   = (int)blockIdx.x * 4 + sub;
    const float4* xr = (const float4*)(x + (size_t)row * K_DIM);

    // 8 float4 per lane, stride 64 (coalesced), all issued up front
    float4 v[8];
    #pragma unroll
    for (int k = 0; k < 8; k++)
        v[k] = __ldcs(&xr[l64 + 64 * k]);

    float s = 0.f, ss = 0.f;
    #pragma unroll
    for (int k = 0; k < 8; k++) {
        s  += v[k].x + v[k].y + v[k].z + v[k].w;
        ss += v[k].x*v[k].x + v[k].y*v[k].y + v[k].z*v[k].z + v[k].w*v[k].w;
    }
    warp_reduce_sum2(s, ss);
    if ((t & 31) == 0) { red[warp] = s; red[warp + 8] = ss; }
    asm volatile("bar.sync %0, 64;" :: "r"(sub) : "memory");
    s  = red[sub * 2] + red[sub * 2 + 1];
    ss = red[sub * 2 + 8] + red[sub * 2 + 9];

    const float invn = 1.0f / (float)K_DIM;
    float mu   = s * invn;
    float rstd = rsqrtf(fmaxf(ss * invn - mu * mu, 0.f) + 1e-5f);

    float amax = 0.f;
    #pragma unroll
    for (int k = 0; k < 8; k++) {
        v[k].x = (v[k].x - mu) * rstd;
        v[k].y = (v[k].y - mu) * rstd;
        v[k].z = (v[k].z - mu) * rstd;
        v[k].w = (v[k].w - mu) * rstd;
        amax = fmaxf(amax, fmaxf(fmaxf(fabsf(v[k].x), fabsf(v[k].y)),
                                 fmaxf(fabsf(v[k].z), fabsf(v[k].w))));
    }
    warp_reduce_max(amax);
    if ((t & 31) == 0) red[warp] = amax;
    asm volatile("bar.sync %0, 64;" :: "r"(sub) : "memory");
    amax = fmaxf(red[sub * 2], red[sub * 2 + 1]);
    amax = fmaxf(amax, 1e-5f);
    float inv = 127.0f / amax;

    char4* dst = (char4*)(g_xq + (size_t)row * K_DIM);
    #pragma unroll
    for (int k = 0; k < 8; k++) {
        char4 c;
        c.x = (char)(int)rintf(v[k].x * inv);
        c.y = (char)(int)rintf(v[k].y * inv);
        c.z = (char)(int)rintf(v[k].z * inv);
        c.w = (char)(int)rintf(v[k].w * inv);
        dst[l64 + 64 * k] = c;
    }
    if (l64 == 0) g_xscale[row] = amax * (1.0f / 127.0f);
}

// ---------------------------------------------------------------------------
// Kernel 2: PERSISTENT int8 tensor-core GEMM via mma.sync.m16n8k32, fused
// dequant.  148 CTAs; each loops over tiles (stride 148).  Mainloop iters
// 13..15 prefetch the NEXT tile's stages 0..2.
// ---------------------------------------------------------------------------
#define BM  128
#define BN  256
#define BKB 128   // K-bytes per stage
#define NIT (K_DIM / BKB)   // 16
#define NSTAGE 4
#define A_BYTES (BM * BKB)                // 16 KB
#define B_BYTES (BN * BKB)                // 32 KB
#define STAGE_BYTES (A_BYTES + B_BYTES)   // 48 KB
#define SMEM_DYN (NSTAGE * STAGE_BYTES)   // 192 KB
#define NTILES ((M_TOK / BM) * (N_DIM / BN))   // 1024
#define GRIDP 148

__device__ __forceinline__ uint32_t smem_u32(const void* p) {
    uint32_t a;
    asm("{ .reg .u64 t; cvta.to.shared.u64 t, %1; cvt.u32.u64 %0, t; }" : "=r"(a) : "l"(p));
    return a;
}

// swizzled byte offset within a [rows x 128B] tile
__device__ __forceinline__ uint32_t swz(int row, int c) {
    return (uint32_t)(row * 128 + ((c ^ (row & 7)) << 4));
}

__device__ __forceinline__ void cp16(uint32_t saddr, const void* g) {
    asm volatile("cp.async.cg.shared.global [%0], [%1], 16;" :: "r"(saddr), "l"(g));
}

__device__ __forceinline__ void ldsm4(uint32_t* r, uint32_t addr) {
    asm volatile("ldmatrix.sync.aligned.m8n8.x4.shared.b16 {%0,%1,%2,%3}, [%4];"
                 : "=r"(r[0]), "=r"(r[1]), "=r"(r[2]), "=r"(r[3]) : "r"(addr));
}

__device__ __forceinline__ void mma_s8(int* c, const uint32_t* a, const uint32_t* b) {
    asm volatile(
        "mma.sync.aligned.m16n8k32.row.col.s32.s8.s8.s32 "
        "{%0,%1,%2,%3}, {%4,%5,%6,%7}, {%8,%9}, {%0,%1,%2,%3};"
        : "+r"(c[0]), "+r"(c[1]), "+r"(c[2]), "+r"(c[3])
        : "r"(a[0]), "r"(a[1]), "r"(a[2]), "r"(a[3]), "r"(b[0]), "r"(b[1]));
}

__global__ __launch_bounds__(256, 1) void gemm_kernel(const float* __restrict__ wscale) {
    extern __shared__ uint8_t smem[];

    const int tid  = threadIdx.x;
    const int wid  = tid >> 5;
    const int lane = tid & 31;
    const int wm   = wid >> 2;          // 0..1 -> m offset wm*64
    const int wn   = wid & 3;           // 0..3 -> n offset wn*64
    const uint32_t sbase = smem_u32(smem);

    // cooperative load of one stage: A 1024 + B 2048 chunks of 16B = 12/thread
    auto load_stage = [&](int st, int bm, int bn, int k0) {
        uint32_t sa = sbase + st * STAGE_BYTES;
        uint32_t sb = sa + A_BYTES;
        #pragma unroll
        for (int i = 0; i < 12; i++) {
            int idx = tid + i * 256;        // 0..3071
            if (idx < 1024) {
                int row = idx >> 3, c = idx & 7;
                cp16(sa + swz(row, c), g_xq + (size_t)(bm + row) * K_DIM + k0 + c * 16);
            } else {
                int j = idx - 1024;
                int row = j >> 3, c = j & 7;
                cp16(sb + swz(row, c), g_w + (size_t)(bn + row) * K_DIM + k0 + c * 16);
            }
        }
    };

    const int lrow = lane & 15;         // ldmatrix row within 16
    const int lchk = lane >> 4;         // ldmatrix chunk select

    int tile = (int)blockIdx.x;

    // first-tile prologue: 3 stages in flight
    {
        int bm = (tile >> 3) * BM, bn = (tile & 7) * BN;
        load_stage(0, bm, bn, 0);
        asm volatile("cp.async.commit_group;" ::: "memory");
        load_stage(1, bm, bn, BKB);
        asm volatile("cp.async.commit_group;" ::: "memory");
        load_stage(2, bm, bn, 2 * BKB);
        asm volatile("cp.async.commit_group;" ::: "memory");
    }

    for (; tile < NTILES; tile += GRIDP) {
        const int bm = (tile >> 3) * BM;
        const int bn = (tile & 7) * BN;
        const int tile2 = tile + GRIDP;
        const bool has_next = tile2 < NTILES;
        const int bm2 = has_next ? (tile2 >> 3) * BM : 0;
        const int bn2 = has_next ? (tile2 & 7) * BN : 0;

        int acc[4][8][4];
        #pragma unroll
        for (int i = 0; i < 4; i++)
            #pragma unroll
            for (int j = 0; j < 8; j++)
                #pragma unroll
                for (int r = 0; r < 4; r++) acc[i][j][r] = 0;

        for (int it = 0; it < NIT; ++it) {
            asm volatile("cp.async.wait_group 2;" ::: "memory");
            __syncthreads();

            // load this tile's stage nt, or prefetch next tile's stage nt-16
            int nt = it + 3;
            if (nt < NIT) {
                load_stage(nt % NSTAGE, bm, bn, nt * BKB);
            } else if (has_next) {
                load_stage(nt % NSTAGE, bm2, bn2, (nt - NIT) * BKB);
            }
            asm volatile("cp.async.commit_group;" ::: "memory");

            const int st = it % NSTAGE;
            const uint32_t sa = sbase + st * STAGE_BYTES;
            const uint32_t sb = sa + A_BYTES;

            #pragma unroll
            for (int ks = 0; ks < 4; ks++) {    // four k32 steps per 128B stage
                uint32_t a[4][4];
                #pragma unroll
                for (int i = 0; i < 4; i++) {
                    int row = wm * 64 + i * 16 + lrow;
                    ldsm4(a[i], sa + swz(row, ks * 2 + lchk));
                }
                uint32_t b[8][2];
                #pragma unroll
                for (int jj = 0; jj < 4; jj++) {
                    uint32_t r[4];
                    int row = wn * 64 + jj * 16 + lrow;
                    ldsm4(r, sb + swz(row, ks * 2 + lchk));
                    b[jj*2][0]   = r[0]; b[jj*2][1]   = r[2];
                    b[jj*2+1][0] = r[1]; b[jj*2+1][1] = r[3];
                }
                #pragma unroll
                for (int i = 0; i < 4; i++)
                    #pragma unroll
                    for (int j = 0; j < 8; j++)
                        mma_s8(acc[i][j], a[i], b[j]);
            }
        }

        // epilogue (next tile's stages 0..2 already streaming in)
        #pragma unroll
        for (int i = 0; i < 4; i++) {
            int r0 = bm + wm * 64 + i * 16 + (lane >> 2);
            float st0 = g_xscale[r0];
            float st1 = g_xscale[r0 + 8];
            #pragma unroll
            for (int j = 0; j < 8; j++) {
                int col = bn + wn * 64 + j * 8 + (lane & 3) * 2;
                float w0 = __ldg(&wscale[col]);
                float w1 = __ldg(&wscale[col + 1]);
                __half2 h0 = __floats2half2_rn((float)acc[i][j][0] * st0 * w0,
                                               (float)acc[i][j][1] * st0 * w1);
                __half2 h1 = __floats2half2_rn((float)acc[i][j][2] * st1 * w0,
                                               (float)acc[i][j][3] * st1 * w1);
                __stcs((uint32_t*)(g_vh + (size_t)r0 * N_DIM + col),
                       *reinterpret_cast<uint32_t*>(&h0));
                __stcs((uint32_t*)(g_vh + (size_t)(r0 + 8) * N_DIM + col),
                       *reinterpret_cast<uint32_t*>(&h1));
            }
        }
    }
}

// ---------------------------------------------------------------------------
// Kernel 3: output LayerNorm over the f16 dequantized GEMM result.
// WARP-PER-ROW: one warp owns one token row (64 halves/lane), zero barriers.
// Stats in f32.
// ---------------------------------------------------------------------------
__global__ __launch_bounds__(256) void ln_out_kernel(float* __restrict__ out) {
    const int t    = threadIdx.x;
    const int wid  = t >> 5;
    const int lane = t & 31;
    const int row  = (int)blockIdx.x * 8 + wid;

    const uint4* vr = (const uint4*)(g_vh + (size_t)row * N_DIM);   // 256 uint4/row

    uint4 p[8];
    #pragma unroll
    for (int k = 0; k < 8; k++)
        p[k] = __ldcs(&vr[lane + 32 * k]);

    float s = 0.f, ss = 0.f;
    #pragma unroll
    for (int k = 0; k < 8; k++) {
        float2 f0 = __half22float2(*reinterpret_cast<__half2*>(&p[k].x));
        float2 f1 = __half22float2(*reinterpret_cast<__half2*>(&p[k].y));
        float2 f2 = __half22float2(*reinterpret_cast<__half2*>(&p[k].z));
        float2 f3 = __half22float2(*reinterpret_cast<__half2*>(&p[k].w));
        s  += f0.x + f0.y + f1.x + f1.y + f2.x + f2.y + f3.x + f3.y;
        ss += f0.x*f0.x + f0.y*f0.y + f1.x*f1.x + f1.y*f1.y
            + f2.x*f2.x + f2.y*f2.y + f3.x*f3.x + f3.y*f3.y;
    }
    warp_reduce_sum2(s, ss);

    const float invn = 1.0f / (float)N_DIM;
    float mu   = s * invn;
    float rstd = rsqrtf(fmaxf(ss * invn - mu * mu, 0.f) + 1e-5f);

    // normalize + store: uint4 k covers halves [(lane+32k)*8 .. +7]
    float4* dst = (float4*)(out + (size_t)row * N_DIM);
    #pragma unroll
    for (int k = 0; k < 8; k++) {
        int f4i = 2 * (lane + 32 * k);
        float2 f0 = __half22float2(*reinterpret_cast<__half2*>(&p[k].x));
        float2 f1 = __half22float2(*reinterpret_cast<__half2*>(&p[k].y));
        float2 f2 = __half22float2(*reinterpret_cast<__half2*>(&p[k].z));
        float2 f3 = __half22float2(*reinterpret_cast<__half2*>(&p[k].w));
        float4 o;
        o.x = (f0.x - mu) * rstd; o.y = (f0.y - mu) * rstd;
        o.z = (f1.x - mu) * rstd; o.w = (f1.y - mu) * rstd;
        __stcs(&dst[f4i], o);
        o.x = (f2.x - mu) * rstd; o.y = (f2.y - mu) * rstd;
        o.z = (f3.x - mu) * rstd; o.w = (f3.y - mu) * rstd;
        __stcs(&dst[f4i + 1], o);
    }
}

// ---------------------------------------------------------------------------
// Launch (3 kernels: ln_quant+pack fused, persistent gemm+dequant, ln_out)
// ---------------------------------------------------------------------------
extern "C" void kernel_launch(void* const* d_in, const int* in_sizes, int n_in,
                              void* d_out, int out_size) {
    const float* x  = (const float*)d_in[0];          // [4,4096,2048] f32
    const int*   wt = (const int*)d_in[1];            // [2048,2048] i32 ternary
    const float* ws = (const float*)d_in[2];          // [2048] f32
    float* out = (float*)d_out;                       // [4,4096,2048] f32

    cudaFuncSetAttribute(gemm_kernel, cudaFuncAttributeMaxDynamicSharedMemorySize, SMEM_DYN);

    ln_quant_kernel<<<LNQ_BLOCKS + PACK_BLOCKS, 256>>>(x, wt);
    gemm_kernel<<<GRIDP, 256, SMEM_DYN>>>(ws);
    ln_out_kernel<<<M_TOK / 8, 256>>>(out);
}